// round 15
// baseline (speedup 1.0000x reference)
#include <cuda_runtime.h>
#include <cuda_fp16.h>
#include <cstdint>

// ============================================================================
// Fully-fused Forecaster (R8 structure, best known) + minimal-chain epilogue:
//   stage1: x  @ W0i (K=64)  + bias0 -> h1 (SMEM), c1 (regs)
//   stage2: h1 @ W0h (K=128) + mug   -> h2 (SMEM)          [c1 regs]
//   stage3: h1 @ W1i (K=128) + bias1 -> h1p (SMEM), c1p (regs)
//   stage4: h2 @ W1i + h1p @ W1h + bias1 -> relu -> FC -> out
// v8: weights/bias/mug pre-scaled by -log2e (i,f,o) / -2log2e (g) so every
// sigmoid is rcp(1+ex2(acc+bias)) with no leading multiply; tanh via one FMA.
// Chains stay independent per activation (R12's batching regressed).
// ============================================================================

#define NROWS 65536

__device__ __align__(16) __half d_W0i[512 * 64];
__device__ __align__(16) __half d_W0h[512 * 128];
__device__ __align__(16) __half d_W1i[512 * 128];
__device__ __align__(16) __half d_W1h[512 * 128];
__device__ float d_bias0p[512], d_bias1p[512];
__device__ float d_mug[64 * 512];
__device__ float d_fcw[128];
__device__ float d_fcb_v;
__device__ __align__(16) __half d_x16[NROWS * 64];

#define L2E  1.4426950408889634f
#define L2E2 2.8853900817779268f

// ---------------- helpers ----------------
__device__ __forceinline__ uint32_t smem_u32(const void* p) {
    uint32_t a;
    asm("{ .reg .u64 t; cvta.to.shared.u64 t, %1; cvt.u32.u64 %0, t; }"
        : "=r"(a) : "l"(p));
    return a;
}
__device__ __forceinline__ void ldsm4(uint32_t* r, uint32_t a) {
    asm volatile("ldmatrix.sync.aligned.m8n8.x4.shared.b16 {%0,%1,%2,%3}, [%4];"
                 : "=r"(r[0]), "=r"(r[1]), "=r"(r[2]), "=r"(r[3]) : "r"(a));
}
__device__ __forceinline__ void mma16816(float* d, const uint32_t* a, const uint32_t* b) {
    asm volatile(
        "mma.sync.aligned.m16n8k16.row.col.f32.f16.f16.f32 "
        "{%0,%1,%2,%3}, {%4,%5,%6,%7}, {%8,%9}, {%0,%1,%2,%3};"
        : "+f"(d[0]), "+f"(d[1]), "+f"(d[2]), "+f"(d[3])
        : "r"(a[0]), "r"(a[1]), "r"(a[2]), "r"(a[3]), "r"(b[0]), "r"(b[1]));
}
#define CP_COMMIT() asm volatile("cp.async.commit_group;" ::: "memory")
#define CP_WAIT0()  asm volatile("cp.async.wait_group 0;" ::: "memory")

__device__ __forceinline__ float ex2f(float x) {
    float r;
    asm("ex2.approx.f32 %0, %1;" : "=f"(r) : "f"(x));
    return r;
}
__device__ __forceinline__ float rcpf(float x) {
    float r;
    asm("rcp.approx.f32 %0, %1;" : "=f"(r) : "f"(x));
    return r;
}

// LSTM cell on pre-scaled gates (gi,gf,go: -L2E*g ; gg: -2*L2E*g).
// sigma(g) = rcp(1 + ex2(ghat)); tanh via (1-e)*r = fma(-e,r,r).
template <bool HASC>
__device__ __forceinline__ float lstm_cell(float gi, float gf, float gg, float go,
                                           float cp, float& cout) {
    const float si = rcpf(1.0f + ex2f(gi));
    const float e3 = ex2f(gg);
    const float r3 = rcpf(1.0f + e3);
    const float tg = fmaf(-e3, r3, r3);
    float cn;
    if (HASC) {
        const float sf = rcpf(1.0f + ex2f(gf));
        cn = fmaf(sf, cp, si * tg);
    } else {
        cn = si * tg;
    }
    const float so = rcpf(1.0f + ex2f(go));
    const float e5 = ex2f(-L2E2 * cn);
    const float r5 = rcpf(1.0f + e5);
    cout = cn;
    return so * fmaf(-e5, r5, r5);
}

// packed-column mapping: c' -> (gate t, unit j)
__device__ __forceinline__ void cmap(int c_, int& gate, int& j) {
    int nc = c_ >> 7, cg = (c_ >> 5) & 3, t = (c_ >> 3) & 3, ct = c_ & 7;
    gate = t;
    j = nc * 32 + cg * 8 + ct;
}

// ============================================================================
// Prep kernels (weights/bias/mug pre-scaled)
// ============================================================================
__global__ void prep_pack(const float* __restrict__ Wih0, const float* __restrict__ Whh0,
                          const float* __restrict__ Wih1, const float* __restrict__ Whh1,
                          const float* __restrict__ bih0, const float* __restrict__ bhh0,
                          const float* __restrict__ bih1, const float* __restrict__ bhh1,
                          const float* __restrict__ fcw, const float* __restrict__ fcb) {
    int i = blockIdx.x * 256 + threadIdx.x;    // 65536 threads
    int c_ = i >> 7, k = i & 127;
    int gate, j;
    cmap(c_, gate, j);
    int G = gate * 128 + j;
    const float sc = (gate == 2) ? -L2E2 : -L2E;
    d_W0h[c_ * 128 + k] = __float2half_rn(Whh0[G * 128 + k] * sc);
    d_W1i[c_ * 128 + k] = __float2half_rn(Wih1[G * 128 + k] * sc);
    d_W1h[c_ * 128 + k] = __float2half_rn(Whh1[G * 128 + k] * sc);
    if (k < 64) d_W0i[c_ * 64 + k] = __float2half_rn(Wih0[G * 64 + k] * sc);
    if (k == 0) {
        d_bias0p[c_] = (bih0[G] + bhh0[G]) * sc;
        d_bias1p[c_] = (bih1[G] + bhh1[G]) * sc;
    }
    if (i < 128) d_fcw[i] = fcw[i];
    if (i == 0) d_fcb_v = fcb[0];
}

__global__ void prep_mug(const float* __restrict__ mu,
                         const float* __restrict__ Wih0,
                         const float* __restrict__ bih0,
                         const float* __restrict__ bhh0) {
    __shared__ float mur[64];
    int c_ = threadIdx.x;
    if (c_ < 64) mur[c_] = mu[blockIdx.x * 64 + c_];
    __syncthreads();
    int gate, j;
    cmap(c_, gate, j);
    int G = gate * 128 + j;
    float s = bih0[G] + bhh0[G];
    const float* wr = Wih0 + G * 64;
#pragma unroll
    for (int k = 0; k < 64; k++) s = fmaf(mur[k], wr[k], s);
    const float sc = (gate == 2) ? -L2E2 : -L2E;
    d_mug[blockIdx.x * 512 + c_] = s * sc;
}

__global__ void prep_x(const float* __restrict__ x) {
    int i = blockIdx.x * 256 + threadIdx.x;
    float4 v = reinterpret_cast<const float4*>(x)[i];
    __half2 p01 = __floats2half2_rn(v.x, v.y);
    __half2 p23 = __floats2half2_rn(v.z, v.w);
    reinterpret_cast<uint2*>(d_x16)[i] =
        make_uint2(*reinterpret_cast<uint32_t*>(&p01), *reinterpret_cast<uint32_t*>(&p23));
}

// ============================================================================
// cp.async SMEM fill: 128 rows x KT fp16, stride ST = 2*KT+16
// ============================================================================
template <int KT>
__device__ __forceinline__ void cp_fill(uint32_t sdst, const __half* __restrict__ g,
                                        int row0, int tid) {
    constexpr int ST = KT * 2 + 16;
    constexpr int CPR = KT / 8;
    constexpr int ITER = 128 * CPR / 512;
#pragma unroll
    for (int t = 0; t < ITER; t++) {
        int e = tid + t * 512;
        int row = e / CPR;
        int kq = (e % CPR) * 8;
        uint32_t d = sdst + (uint32_t)row * ST + (uint32_t)kq * 2;
        const void* s = g + (size_t)(row0 + row) * KT + kq;
        asm volatile("cp.async.cg.shared.global [%0], [%1], 16;" :: "r"(d), "l"(s));
    }
}

// ============================================================================
// MMA sweep: warp tile 32 rows x 32 packed cols
// ============================================================================
template <int KT>
__device__ __forceinline__ void sweep(uint32_t sA, uint32_t sB, int lane,
                                      int m0, int n0, float (&acc)[2][4][4]) {
    constexpr int ST = KT * 2 + 16;
    const uint32_t lrow = (uint32_t)(lane & 15);
    const uint32_t lhi = (uint32_t)(lane >> 4) * 16u;
    const uint32_t aB0 = sA + (m0 + lrow) * ST + lhi;
    const uint32_t aB1 = aB0 + 16 * ST;
    const uint32_t bB0 = sB + (n0 + lrow) * ST + lhi;
    const uint32_t bB1 = bB0 + 16 * ST;
#pragma unroll
    for (int kc = 0; kc < KT / 16; kc++) {
        const uint32_t ko = kc * 32;
        uint32_t a0[4], a1[4], b0[4], b1[4];
        ldsm4(a0, aB0 + ko);
        ldsm4(a1, aB1 + ko);
        ldsm4(b0, bB0 + ko);
        ldsm4(b1, bB1 + ko);
        uint32_t be0[2] = {b0[0], b0[2]}, bo0[2] = {b0[1], b0[3]};
        uint32_t be1[2] = {b1[0], b1[2]}, bo1[2] = {b1[1], b1[3]};
        mma16816(acc[0][0], a0, be0); mma16816(acc[1][0], a1, be0);
        mma16816(acc[0][1], a0, bo0); mma16816(acc[1][1], a1, bo0);
        mma16816(acc[0][2], a0, be1); mma16816(acc[1][2], a1, be1);
        mma16816(acc[0][3], a0, bo1); mma16816(acc[1][3], a1, bo1);
    }
}

// ============================================================================
// Fused kernel
// ============================================================================
constexpr int ST128 = 272;
constexpr int TILE128 = 128 * ST128;   // 34816 B

__global__ void __launch_bounds__(512, 1) lstm_fused(float* __restrict__ out) {
    extern __shared__ __align__(128) char dsm[];
    __shared__ float s_b0[512], s_b1[512], s_mug[512], s_fcw[128];
    __shared__ float s_fc[4][128];

    const int tid = threadIdx.x, lane = tid & 31, wid = tid >> 5;
    const int rg = wid >> 2, cg = wid & 3, q = lane & 3;
    const int row0 = blockIdx.x * 128;
    const int m0 = rg * 32, n0 = cg * 32;

    const uint32_t s0 = smem_u32(dsm);
    const uint32_t sH1 = s0, sH2 = s0 + TILE128, sH1p = s0 + 2 * TILE128;
    const uint32_t sX = sH1p;                 // overlay: x dead before h1p written
    const uint32_t sB[2] = {s0 + 3 * TILE128, s0 + 4 * TILE128};

    s_b0[tid] = d_bias0p[tid];
    if (tid < 512) { s_b1[tid] = d_bias1p[tid]; s_mug[tid] = d_mug[(row0 >> 10) * 512 + tid]; }
    if (tid < 128) s_fcw[tid] = d_fcw[tid];

    cp_fill<64>(sX, d_x16, row0, tid);
    cp_fill<64>(sB[0], d_W0i, 0, tid);
    CP_COMMIT();

    uint32_t creg[4][4];                      // c as half2, [nc][mt*2+h2]
    int bi = 0;

    auto epi = [&](const float (&acc)[2][4][4], int MODE, const float* addv,
                   uint32_t sDst, int nc, float* fcacc) {
#pragma unroll
        for (int mt = 0; mt < 2; mt++) {
#pragma unroll
            for (int h2 = 0; h2 < 2; h2++) {
                const int rowL = rg * 32 + mt * 16 + (lane >> 2) + h2 * 8;
                const int s = mt * 2 + h2;
                float cprev[2] = {0.0f, 0.0f};
                if (MODE == 2 || MODE == 4) {
                    __half2 cp2 = *reinterpret_cast<__half2*>(&creg[nc][s]);
                    cprev[0] = __low2float(cp2);
                    cprev[1] = __high2float(cp2);
                }
                // float2 bias loads: pairs (u=0,u=1) are adjacent & 8B aligned
                const int bcol = cg * 32 + 2 * q;
                const float2 bI = *reinterpret_cast<const float2*>(addv + bcol);
                const float2 bF = *reinterpret_cast<const float2*>(addv + bcol + 8);
                const float2 bG = *reinterpret_cast<const float2*>(addv + bcol + 16);
                const float2 bO = *reinterpret_cast<const float2*>(addv + bcol + 24);
                float hv[2], cv[2];
#pragma unroll
                for (int u = 0; u < 2; u++) {
                    const float gi = acc[mt][0][h2 * 2 + u] + (u ? bI.y : bI.x);
                    const float gf = acc[mt][1][h2 * 2 + u] + (u ? bF.y : bF.x);
                    const float gg = acc[mt][2][h2 * 2 + u] + (u ? bG.y : bG.x);
                    const float go = acc[mt][3][h2 * 2 + u] + (u ? bO.y : bO.x);
                    if (MODE == 1 || MODE == 3)
                        hv[u] = lstm_cell<false>(gi, gf, gg, go, 0.0f, cv[u]);
                    else
                        hv[u] = lstm_cell<true>(gi, gf, gg, go, cprev[u], cv[u]);
                }
                if (MODE == 4) {
                    const int j0 = nc * 32 + cg * 8 + 2 * q;
                    fcacc[s] = fmaf(fmaxf(hv[0], 0.0f), s_fcw[j0], fcacc[s]);
                    fcacc[s] = fmaf(fmaxf(hv[1], 0.0f), s_fcw[j0 + 1], fcacc[s]);
                } else {
                    __half2 hh = __floats2half2_rn(hv[0], hv[1]);
                    uint32_t addr = sDst + (uint32_t)rowL * ST128
                                  + (uint32_t)(nc * 32 + cg * 8 + 2 * q) * 2;
                    asm volatile("st.shared.b32 [%0], %1;"
                                 :: "r"(addr), "r"(*reinterpret_cast<uint32_t*>(&hh)));
                    if (MODE == 1 || MODE == 3) {
                        __half2 cc = __floats2half2_rn(cv[0], cv[1]);
                        creg[nc][s] = *reinterpret_cast<uint32_t*>(&cc);
                    }
                }
            }
        }
    };

    // ---------------- stage 1 (K=64): x -> h1, c1 ----------------
#pragma unroll
    for (int nc = 0; nc < 4; nc++) {
        CP_WAIT0(); __syncthreads();
        if (nc < 3) cp_fill<64>(sB[bi ^ 1], d_W0i + (nc + 1) * 128 * 64, 0, tid);
        else        cp_fill<128>(sB[bi ^ 1], d_W0h, 0, tid);
        CP_COMMIT();
        float acc[2][4][4] = {};
        sweep<64>(sX, sB[bi], lane, m0, n0, acc);
        epi(acc, 1, s_b0 + nc * 128, sH1, nc, nullptr);
        bi ^= 1;
    }

    // ---------------- stage 2 (K=128): h1 -> h2 (uses c1) ----------------
#pragma unroll
    for (int nc = 0; nc < 4; nc++) {
        CP_WAIT0(); __syncthreads();
        if (nc < 3) cp_fill<128>(sB[bi ^ 1], d_W0h + (nc + 1) * 128 * 128, 0, tid);
        else        cp_fill<128>(sB[bi ^ 1], d_W1i, 0, tid);
        CP_COMMIT();
        float acc[2][4][4] = {};
        sweep<128>(sH1, sB[bi], lane, m0, n0, acc);
        epi(acc, 2, s_mug + nc * 128, sH2, nc, nullptr);
        bi ^= 1;
    }

    // ---------------- stage 3 (K=128): h1 -> h1p, c1p ----------------
#pragma unroll
    for (int nc = 0; nc < 4; nc++) {
        CP_WAIT0(); __syncthreads();
        if (nc < 3) cp_fill<128>(sB[bi ^ 1], d_W1i + (nc + 1) * 128 * 128, 0, tid);
        else        cp_fill<128>(sB[bi ^ 1], d_W1i, 0, tid);       // stage4 tile 0
        CP_COMMIT();
        float acc[2][4][4] = {};
        sweep<128>(sH1, sB[bi], lane, m0, n0, acc);
        epi(acc, 3, s_b1 + nc * 128, sH1p, nc, nullptr);
        bi ^= 1;
    }

    // ---------------- stage 4 (K=256): h2@W1i + h1p@W1h -> relu -> FC ----------------
    float fcacc[4] = {0.0f, 0.0f, 0.0f, 0.0f};
    float acc4[2][4][4];
#pragma unroll
    for (int t = 0; t < 8; t++) {
        CP_WAIT0(); __syncthreads();
        if (t < 7) {
            const int nt = t + 1;
            const __half* p = (nt & 1) ? (d_W1h + (nt >> 1) * 128 * 128)
                                       : (d_W1i + (nt >> 1) * 128 * 128);
            cp_fill<128>(sB[bi ^ 1], p, 0, tid);
            CP_COMMIT();
        }
        if ((t & 1) == 0) {
#pragma unroll
            for (int a = 0; a < 2; a++)
#pragma unroll
                for (int b = 0; b < 4; b++)
#pragma unroll
                    for (int c = 0; c < 4; c++) acc4[a][b][c] = 0.0f;
        }
        sweep<128>((t & 1) ? sH1p : sH2, sB[bi], lane, m0, n0, acc4);
        if (t & 1) epi(acc4, 4, s_b1 + (t >> 1) * 128, 0, t >> 1, fcacc);
        bi ^= 1;
    }

    // ---- FC reduce ----
#pragma unroll
    for (int s = 0; s < 4; s++) {
        float v = fcacc[s];
        v += __shfl_xor_sync(0xffffffffu, v, 1);
        v += __shfl_xor_sync(0xffffffffu, v, 2);
        if (q == 0) {
            const int rowL = rg * 32 + (s >> 1) * 16 + (lane >> 2) + (s & 1) * 8;
            s_fc[cg][rowL] = v;
        }
    }
    __syncthreads();
    if (tid < 128)
        out[row0 + tid] = s_fc[0][tid] + s_fc[1][tid] + s_fc[2][tid] + s_fc[3][tid] + d_fcb_v;
}

// ============================================================================
// Launch
// ============================================================================
extern "C" void kernel_launch(void* const* d_in, const int* in_sizes, int n_in,
                              void* d_out, int out_size) {
    const float* x    = (const float*)d_in[0];
    const float* mu   = (const float*)d_in[1];
    const float* Wih0 = (const float*)d_in[2];
    const float* Whh0 = (const float*)d_in[3];
    const float* bih0 = (const float*)d_in[4];
    const float* bhh0 = (const float*)d_in[5];
    const float* Wih1 = (const float*)d_in[6];
    const float* Whh1 = (const float*)d_in[7];
    const float* bih1 = (const float*)d_in[8];
    const float* bhh1 = (const float*)d_in[9];
    const float* fcw  = (const float*)d_in[10];
    const float* fcb  = (const float*)d_in[11];
    float* out = (float*)d_out;

    const int SMEM = 5 * TILE128;   // 174080 B
    cudaFuncSetAttribute(lstm_fused, cudaFuncAttributeMaxDynamicSharedMemorySize, SMEM);

    prep_pack<<<256, 256>>>(Wih0, Whh0, Wih1, Whh1, bih0, bhh0, bih1, bhh1, fcw, fcb);
    prep_mug<<<64, 512>>>(mu, Wih0, bih0, bhh0);
    prep_x<<<4096, 256>>>(x);

    lstm_fused<<<512, 512, SMEM>>>(out);
}